// round 12
// baseline (speedup 1.0000x reference)
#include <cuda_runtime.h>
#include <math.h>
#include <stdint.h>

// ---------------------------------------------------------------------------
// Problem constants
// ---------------------------------------------------------------------------
#define N0     6000
#define IND    1536
#define DIM    1024
#define HEADS  8
#define DHEAD  128
#define LMK    512
#define NITERS 6
#define HH     78
#define NF     (HH*HH)       // 6084
#define ADD    (NF - N0)     // 84
#define HT     (NF + 1)      // 6085
#define NP     6144
#define PAD    (NP - HT)     // 59
#define LFAC   (NP / LMK)    // 12

// ---------------------------------------------------------------------------
// Scratch (device globals; no allocation allowed).
// g_wrnd: tf32-rounded copies of raw inputs (data/expert_w/qkv_w/out_w)
// ---------------------------------------------------------------------------
__device__ float g_h[(size_t)HT * DIM];
__device__ float g_xln[(size_t)NP * DIM];
__device__ float g_qkv[(size_t)NP * 3072];
__device__ float g_q[(size_t)HEADS * NP * DHEAD];
__device__ float g_k[(size_t)HEADS * NP * DHEAD];
__device__ float g_v[(size_t)HEADS * NP * DHEAD];
__device__ float g_ql[(size_t)HEADS * LMK * DHEAD];
__device__ float g_kl[(size_t)HEADS * LMK * DHEAD];
__device__ float g_a1[(size_t)HEADS * NP * LMK];
__device__ float g_a3[(size_t)HEADS * LMK * NP];
__device__ float g_a2[(size_t)HEADS * LMK * LMK];
__device__ float g_z[(size_t)HEADS * LMK * LMK];
__device__ float g_z2[(size_t)HEADS * LMK * LMK];
__device__ float g_xz[(size_t)HEADS * LMK * LMK];
__device__ float g_tA[(size_t)HEADS * LMK * LMK];
__device__ float g_av[(size_t)HEADS * LMK * DHEAD];
__device__ float g_zav[(size_t)HEADS * LMK * DHEAD];
__device__ float g_O[(size_t)HEADS * NP * DHEAD];
__device__ float g_merged[(size_t)NP * DIM];
__device__ float g_outp[(size_t)NP * DIM];
__device__ float g_wrnd[(size_t)14000000];
__device__ float g_scal[4];

// ---------------------------------------------------------------------------
// tf32 rounding helper (round-to-nearest-even into fp32 container)
// ---------------------------------------------------------------------------
__device__ __forceinline__ float rnd_tf32(float x) {
    uint32_t r;
    asm("cvt.rna.tf32.f32 %0, %1;" : "=r"(r) : "f"(x));
    return __uint_as_float(r);
}

// rounded copy of a raw tensor (so GEMM truncation becomes exact)
__global__ void rnd_copy(const float* __restrict__ in, float* __restrict__ out, int n) {
    int i = blockIdx.x * blockDim.x + threadIdx.x;
    if (i < n) out[i] = rnd_tf32(in[i]);
}

// ---------------------------------------------------------------------------
// Reductions
// ---------------------------------------------------------------------------
__device__ __forceinline__ float warpSum(float v) {
#pragma unroll
    for (int o = 16; o > 0; o >>= 1) v += __shfl_xor_sync(0xffffffffu, v, o);
    return v;
}
__device__ __forceinline__ float warpMax(float v) {
#pragma unroll
    for (int o = 16; o > 0; o >>= 1) v = fmaxf(v, __shfl_xor_sync(0xffffffffu, v, o));
    return v;
}
__device__ float blockSum(float v, float* sh) {
    int lane = threadIdx.x & 31, wid = threadIdx.x >> 5;
    v = warpSum(v);
    __syncthreads();
    if (lane == 0) sh[wid] = v;
    __syncthreads();
    int nw = (blockDim.x + 31) >> 5;
    if (threadIdx.x < 32) {
        float r = (threadIdx.x < nw) ? sh[threadIdx.x] : 0.f;
        r = warpSum(r);
        if (threadIdx.x == 0) sh[0] = r;
    }
    __syncthreads();
    return sh[0];
}
__device__ float blockMax(float v, float* sh) {
    int lane = threadIdx.x & 31, wid = threadIdx.x >> 5;
    v = warpMax(v);
    __syncthreads();
    if (lane == 0) sh[wid] = v;
    __syncthreads();
    int nw = (blockDim.x + 31) >> 5;
    if (threadIdx.x < 32) {
        float r = (threadIdx.x < nw) ? sh[threadIdx.x] : -3.4e38f;
        r = warpMax(r);
        if (threadIdx.x == 0) sh[0] = r;
    }
    __syncthreads();
    return sh[0];
}

// ---------------------------------------------------------------------------
// Tensor-core GEMM (tf32 mma.sync, fp32 accumulate), cp.async 8-stage pipeline
// Block tile 128x128x16, 256 threads = 8 warps (2x4), warp tile 64x32.
// 8 stages / 7-tile prefetch lead: ~1800 cycles of in-flight loads vs ~260
// cycles compute per tile -> full DRAM latency hiding at 1 CTA/SM.
// All operands are pre-rounded to tf32, so the MMA's truncation is exact.
// ---------------------------------------------------------------------------
#define SPA 20
#define SPB 136
#define ASZ (128 * SPA)
#define BSZ_T (128 * SPA)
#define BSZ_N (16 * SPB)
#define STAGES 8

static constexpr int SMEM_T_BYTES = STAGES * (ASZ + BSZ_T) * 4;  // 163840
static constexpr int SMEM_N_BYTES = STAGES * (ASZ + BSZ_N) * 4;  // 151552

__device__ __forceinline__ void cp16(uint32_t saddr, const void* gaddr, int sz) {
    asm volatile("cp.async.cg.shared.global [%0], [%1], 16, %2;"
                 :: "r"(saddr), "l"(gaddr), "r"(sz) : "memory");
}
__device__ __forceinline__ void cp_commit() {
    asm volatile("cp.async.commit_group;" ::: "memory");
}
__device__ __forceinline__ void cp_wait6() {
    asm volatile("cp.async.wait_group 6;" ::: "memory");
}
__device__ __forceinline__ void mma8(float* c, const uint32_t* a, const uint32_t* b) {
    asm volatile(
        "mma.sync.aligned.m16n8k8.row.col.f32.tf32.tf32.f32 "
        "{%0,%1,%2,%3}, {%4,%5,%6,%7}, {%8,%9}, {%0,%1,%2,%3};"
        : "+f"(c[0]), "+f"(c[1]), "+f"(c[2]), "+f"(c[3])
        : "r"(a[0]), "r"(a[1]), "r"(a[2]), "r"(a[3]), "r"(b[0]), "r"(b[1]));
}

template <bool TRANSB>
__global__ __launch_bounds__(256) void gemm_tc(
    const float* __restrict__ A, const float* __restrict__ B,
    float* __restrict__ C, int M, int N, int K,
    int lda, int ldb, int ldc,
    long long sA, long long sB, long long sC,
    const float* __restrict__ bias, float alpha, float diag_c,
    float* __restrict__ C2, float diag2, int rndC)
{
    A += (long long)blockIdx.z * sA;
    B += (long long)blockIdx.z * sB;
    C += (long long)blockIdx.z * sC;
    if (C2) C2 += (long long)blockIdx.z * sC;

    extern __shared__ uint32_t smem[];
    constexpr int BSZ = TRANSB ? BSZ_T : BSZ_N;
    constexpr int STG = ASZ + BSZ;
    const uint32_t smem_base = (uint32_t)__cvta_generic_to_shared(smem);

    const int tid  = threadIdx.x;
    const int lane = tid & 31;
    const int warp = tid >> 5;
    const int wm   = warp & 1;
    const int wn   = warp >> 1;
    const int m0   = blockIdx.y * 128;
    const int n0   = blockIdx.x * 128;
    const int ntile = K >> 4;

    float acc[4][4][4];
#pragma unroll
    for (int i = 0; i < 4; i++)
#pragma unroll
        for (int j = 0; j < 4; j++)
#pragma unroll
            for (int l = 0; l < 4; l++) acc[i][j][l] = 0.f;

    auto prefetch = [&](int kt) {
        const int st = kt & (STAGES - 1);
        const int koff = kt << 4;
        const uint32_t sa = smem_base + (uint32_t)(st * STG) * 4u;
        const uint32_t sb = sa + (uint32_t)ASZ * 4u;
#pragma unroll
        for (int i = 0; i < 2; i++) {
            const int chunk = (tid << 1) + i;
            {
                const int row = chunk >> 2, kc = (chunk & 3) << 2;
                const float* src = A + (long long)(m0 + row) * lda + koff + kc;
                cp16(sa + (uint32_t)(row * SPA + kc) * 4u, src, (m0 + row < M) ? 16 : 0);
            }
            if (TRANSB) {
                const int row = chunk >> 2, kc = (chunk & 3) << 2;
                const float* src = B + (long long)(n0 + row) * ldb + koff + kc;
                cp16(sb + (uint32_t)(row * SPA + kc) * 4u, src, 16);
            } else {
                const int kr = chunk >> 5, nc = (chunk & 31) << 2;
                const float* src = B + (long long)(koff + kr) * ldb + n0 + nc;
                cp16(sb + (uint32_t)(kr * SPB + nc) * 4u, src, 16);
            }
        }
        cp_commit();
    };

    // prologue: 7 tiles in flight
#pragma unroll
    for (int p = 0; p < 7; p++) {
        if (p < ntile) prefetch(p);
        else cp_commit();
    }

    for (int kt = 0; kt < ntile; kt++) {
        cp_wait6();
        __syncthreads();
        const int st = kt & (STAGES - 1);
        const uint32_t* as = smem + st * STG;
        const uint32_t* bs = as + ASZ;
#pragma unroll
        for (int kk = 0; kk < 2; kk++) {
            const int c = (kk << 3) + (lane & 3);
            uint32_t af[4][4];
#pragma unroll
            for (int mf = 0; mf < 4; mf++) {
                const int r = (wm << 6) + (mf << 4) + (lane >> 2);
                af[mf][0] = as[(r    ) * SPA + c    ];
                af[mf][1] = as[(r + 8) * SPA + c    ];
                af[mf][2] = as[(r    ) * SPA + c + 4];
                af[mf][3] = as[(r + 8) * SPA + c + 4];
            }
            uint32_t bf[4][2];
#pragma unroll
            for (int nf = 0; nf < 4; nf++) {
                const int n = (wn << 5) + (nf << 3) + (lane >> 2);
                if (TRANSB) {
                    bf[nf][0] = bs[n * SPA + c    ];
                    bf[nf][1] = bs[n * SPA + c + 4];
                } else {
                    bf[nf][0] = bs[(c    ) * SPB + n];
                    bf[nf][1] = bs[(c + 4) * SPB + n];
                }
            }
#pragma unroll
            for (int mf = 0; mf < 4; mf++)
#pragma unroll
                for (int nf = 0; nf < 4; nf++)
                    mma8(acc[mf][nf], af[mf], bf[nf]);
        }
        if (kt + 7 < ntile) prefetch(kt + 7);
    }

    // epilogue
#pragma unroll
    for (int mf = 0; mf < 4; mf++) {
        const int rb = m0 + (wm << 6) + (mf << 4) + (lane >> 2);
#pragma unroll
        for (int nf = 0; nf < 4; nf++) {
            const int cb = n0 + (wn << 5) + (nf << 3) + ((lane & 3) << 1);
#pragma unroll
            for (int half = 0; half < 2; half++) {
                const int rr = rb + half * 8;
                if (rr >= M) continue;
#pragma unroll
                for (int e = 0; e < 2; e++) {
                    const int cc = cb + e;
                    float v = alpha * acc[mf][nf][half * 2 + e];
                    if (bias) v += bias[cc];
                    if (diag_c != 0.f && rr == cc) v += diag_c;
                    C[(long long)rr * ldc + cc] = rndC ? rnd_tf32(v) : v;
                    if (C2) {
                        float w = ((rr == cc) ? diag2 : 0.f) - v;
                        C2[(long long)rr * ldc + cc] = rndC ? rnd_tf32(w) : w;
                    }
                }
            }
        }
    }
}

// deterministic split-K reduce; output rounded (feeds zav GEMM)
__global__ void add3(const float* __restrict__ p0, const float* __restrict__ p1,
                     const float* __restrict__ p2, float* __restrict__ out, int n) {
    int i = blockIdx.x * blockDim.x + threadIdx.x;
    if (i < n) out[i] = rnd_tf32(p0[i] + p1[i] + p2[i]);
}

// ---------------------------------------------------------------------------
// Elementwise / reduction kernels (GEMM-feeding outputs tf32-rounded)
// ---------------------------------------------------------------------------
__global__ void moe_combine(const float* __restrict__ data, const float* __restrict__ wg,
                            const float* __restrict__ C, const float* __restrict__ eb,
                            float* __restrict__ hext) {
    int n = blockIdx.x;
    __shared__ float sh[32];
    float l0 = 0.f, l1 = 0.f, l2 = 0.f;
    const float* x = data + (long long)n * IND;
    for (int f = threadIdx.x; f < IND; f += blockDim.x) {
        float xv = x[f];
        l0 += xv * wg[f * 3 + 0];
        l1 += xv * wg[f * 3 + 1];
        l2 += xv * wg[f * 3 + 2];
    }
    l0 = blockSum(l0, sh);
    l1 = blockSum(l1, sh);
    l2 = blockSum(l2, sh);
    float m = fmaxf(l0, fmaxf(l1, l2));
    float e0 = __expf(l0 - m), e1 = __expf(l1 - m), e2 = __expf(l2 - m);
    float inv = 1.f / (e0 + e1 + e2);
    float gg0 = e0 * inv, gg1 = e1 * inv, gg2 = e2 * inv;
    const float* Cr = C + (long long)n * 3072;
    for (int o = threadIdx.x; o < DIM; o += blockDim.x) {
        float r = gg0 * fmaxf(Cr[o] + eb[o], 0.f)
                + gg1 * fmaxf(Cr[1024 + o] + eb[1024 + o], 0.f)
                + gg2 * fmaxf(Cr[2048 + o] + eb[2048 + o], 0.f);
        hext[(long long)(1 + n) * DIM + o] = r;
        if (n < ADD) hext[(long long)(1 + N0 + n) * DIM + o] = r;
    }
}

__global__ void set_cls(float* hext, const float* __restrict__ cls) {
    int c = blockIdx.x * blockDim.x + threadIdx.x;
    if (c < DIM) hext[c] = cls[c];
}

__global__ void ln_pad(const float* __restrict__ h, float* __restrict__ out,
                       const float* __restrict__ g, const float* __restrict__ b) {
    int r = blockIdx.x;
    float* o = out + (long long)r * DIM;
    if (r < PAD) {
        for (int c = threadIdx.x; c < DIM; c += blockDim.x) o[c] = 0.f;
        return;
    }
    const float* x = h + (long long)(r - PAD) * DIM;
    __shared__ float sh[32];
    float s = 0.f, s2 = 0.f;
    float xv[4];
#pragma unroll
    for (int i = 0; i < 4; i++) {
        float v = x[threadIdx.x + i * 256];
        xv[i] = v; s += v; s2 += v * v;
    }
    s = blockSum(s, sh);
    s2 = blockSum(s2, sh);
    float mu = s / DIM;
    float var = fmaxf(s2 / DIM - mu * mu, 0.f);
    float rstd = rsqrtf(var + 1e-5f);
#pragma unroll
    for (int i = 0; i < 4; i++) {
        int c = threadIdx.x + i * 256;
        o[c] = rnd_tf32((xv[i] - mu) * rstd * g[c] + b[c]);
    }
}

__global__ void split_qkv(const float* __restrict__ qkv, float* __restrict__ q,
                          float* __restrict__ k, float* __restrict__ v) {
    int n = blockIdx.x;
    const float* row = qkv + (long long)n * 3072;
    for (int c = threadIdx.x; c < 3072; c += blockDim.x) {
        float val = row[c];
        int which = c >> 10, cc = c & 1023;
        int h = cc >> 7, d = cc & 127;
        long long idx = ((long long)h * NP + n) * DHEAD + d;
        if (which == 0)      q[idx] = rnd_tf32(val * 0.08838834764831845f);
        else if (which == 1) k[idx] = rnd_tf32(val);
        else                 v[idx] = rnd_tf32(val);
    }
}

__global__ void landmarks(const float* __restrict__ q, float* __restrict__ ql) {
    int i = blockIdx.x, h = blockIdx.y, d = threadIdx.x;
    const float* base = q + ((long long)h * NP + (long long)i * LFAC) * DHEAD + d;
    float s = 0.f;
#pragma unroll
    for (int j = 0; j < LFAC; j++) s += base[(long long)j * DHEAD];
    ql[((long long)h * LMK + i) * DHEAD + d] = rnd_tf32(s * (1.f / LFAC));
}

// single-pass register softmax: 1 read + 1 write; output tf32-rounded.
template <int MAXC>
__global__ void row_softmax_r(float* __restrict__ X, int ncols) {
    float* x = X + (long long)blockIdx.x * ncols;
    __shared__ float sh[32];
    float loc[MAXC];
    const int nit = ncols >> 8;   // blockDim == 256
    float m = -3.4e38f;
#pragma unroll
    for (int i = 0; i < MAXC; i++) {
        if (i >= nit) break;
        loc[i] = x[threadIdx.x + (i << 8)];
        m = fmaxf(m, loc[i]);
    }
    m = blockMax(m, sh);
    float s = 0.f;
#pragma unroll
    for (int i = 0; i < MAXC; i++) {
        if (i >= nit) break;
        loc[i] = __expf(loc[i] - m);
        s += loc[i];
    }
    s = blockSum(s, sh);
    float inv = 1.f / s;
#pragma unroll
    for (int i = 0; i < MAXC; i++) {
        if (i >= nit) break;
        x[threadIdx.x + (i << 8)] = rnd_tf32(loc[i] * inv);
    }
}

__global__ void scal_init(float* scal) {
    if (threadIdx.x < 4) scal[threadIdx.x] = 0.f;
}

__global__ void a2_scal(const float* __restrict__ a2, float* scal) {
    int h = blockIdx.x;
    const float* A = a2 + (long long)h * LMK * LMK;
    int j = threadIdx.x;
    float rs = 0.f, cs = 0.f;
    for (int c = 0; c < LMK; c++) rs += A[(long long)j * LMK + c];
    for (int r = 0; r < LMK; r++) cs += A[(long long)r * LMK + j];
    __shared__ float sh[32];
    float rm = blockMax(rs, sh);
    float cm = blockMax(cs, sh);
    if (threadIdx.x == 0) {
        atomicMax((int*)&scal[0], __float_as_int(rm));
        atomicMax((int*)&scal[1], __float_as_int(cm));
    }
}

__global__ void zinit(const float* __restrict__ a2, float* __restrict__ z,
                      const float* __restrict__ scal) {
    int h = blockIdx.y, i = blockIdx.x;
    float inv = 1.f / (scal[0] * scal[1]);
    const float* A = a2 + (long long)h * LMK * LMK;
    float* Z = z + (long long)h * LMK * LMK;
    for (int j = threadIdx.x; j < LMK; j += blockDim.x)
        Z[(long long)i * LMK + j] = rnd_tf32(A[(long long)j * LMK + i] * inv);
}

__global__ void res_conv_add(const float* __restrict__ v, const float* __restrict__ w,
                             float* __restrict__ O) {
    int n = blockIdx.x, h = blockIdx.y, d = threadIdx.x;
    float acc = 0.f;
#pragma unroll
    for (int t = 0; t < 33; t++) {
        int nn = n + t - 16;
        if (nn >= 0 && nn < NP)
            acc += w[h * 33 + t] * v[((long long)h * NP + nn) * DHEAD + d];
    }
    O[((long long)h * NP + n) * DHEAD + d] += acc;
}

// merged feeds the out-proj GEMM: round
__global__ void merge_heads(const float* __restrict__ O, float* __restrict__ M_) {
    int n = blockIdx.x;
    for (int c = threadIdx.x; c < DIM; c += blockDim.x) {
        int h = c >> 7, d = c & 127;
        M_[(long long)n * DIM + c] = rnd_tf32(O[((long long)h * NP + n) * DHEAD + d]);
    }
}

__global__ void resid_add(float* __restrict__ h, const float* __restrict__ outp) {
    long long i = (long long)blockIdx.x * blockDim.x + threadIdx.x;
    if (i < (long long)HT * DIM) h[i] += outp[(long long)PAD * DIM + i];
}

__global__ void copy_feat(const float* __restrict__ h, float* __restrict__ f) {
    int s = blockIdx.x;
    for (int c = threadIdx.x; c < DIM; c += blockDim.x)
        f[(long long)s * DIM + c] = h[(long long)(1 + s) * DIM + c];
}

__global__ void ppeg_conv(float* __restrict__ h, const float* __restrict__ f,
                          const float* __restrict__ w7, const float* __restrict__ b7,
                          const float* __restrict__ w5, const float* __restrict__ b5,
                          const float* __restrict__ w3, const float* __restrict__ b3) {
    int s = blockIdx.x;
    int i = s / HH, j = s % HH;
    for (int c = threadIdx.x; c < DIM; c += blockDim.x) {
        float acc = f[(long long)s * DIM + c] + b7[c] + b5[c] + b3[c];
#pragma unroll
        for (int u = 0; u < 7; u++) {
            int ii = i + u - 3;
            if (ii < 0 || ii >= HH) continue;
#pragma unroll
            for (int vv = 0; vv < 7; vv++) {
                int jj = j + vv - 3;
                if (jj < 0 || jj >= HH) continue;
                acc += w7[c * 49 + u * 7 + vv] * f[(long long)(ii * HH + jj) * DIM + c];
            }
        }
#pragma unroll
        for (int u = 0; u < 5; u++) {
            int ii = i + u - 2;
            if (ii < 0 || ii >= HH) continue;
#pragma unroll
            for (int vv = 0; vv < 5; vv++) {
                int jj = j + vv - 2;
                if (jj < 0 || jj >= HH) continue;
                acc += w5[c * 25 + u * 5 + vv] * f[(long long)(ii * HH + jj) * DIM + c];
            }
        }
#pragma unroll
        for (int u = 0; u < 3; u++) {
            int ii = i + u - 1;
            if (ii < 0 || ii >= HH) continue;
#pragma unroll
            for (int vv = 0; vv < 3; vv++) {
                int jj = j + vv - 1;
                if (jj < 0 || jj >= HH) continue;
                acc += w3[c * 9 + u * 3 + vv] * f[(long long)(ii * HH + jj) * DIM + c];
            }
        }
        h[(long long)(1 + s) * DIM + c] = acc;
    }
}

__global__ void final_head(const float* __restrict__ h, const float* __restrict__ g,
                           const float* __restrict__ b, const float* __restrict__ fw,
                           const float* __restrict__ fb, float* __restrict__ out,
                           int out_size) {
    __shared__ float sh[32];
    float s = 0.f, s2 = 0.f;
    float xv[4];
#pragma unroll
    for (int i = 0; i < 4; i++) {
        float v = h[threadIdx.x + i * 256];
        xv[i] = v; s += v; s2 += v * v;
    }
    s = blockSum(s, sh);
    s2 = blockSum(s2, sh);
    float mu = s / DIM;
    float var = fmaxf(s2 / DIM - mu * mu, 0.f);
    float rstd = rsqrtf(var + 1e-5f);
    float d0 = 0.f, d1 = 0.f;
#pragma unroll
    for (int i = 0; i < 4; i++) {
        int c = threadIdx.x + i * 256;
        float xn = (xv[i] - mu) * rstd * g[c] + b[c];
        d0 += xn * fw[c];
        d1 += xn * fw[DIM + c];
    }
    d0 = blockSum(d0, sh);
    d1 = blockSum(d1, sh);
    if (threadIdx.x == 0) {
        float l0 = d0 + fb[0], l1 = d1 + fb[1];
        float m = fmaxf(l0, l1);
        float e0 = expf(l0 - m), e1 = expf(l1 - m);
        float inv = 1.f / (e0 + e1);
        float vals[5] = { l0, l1, e0 * inv, e1 * inv, (l1 > l0) ? 1.f : 0.f };
        for (int i = 0; i < 5 && i < out_size; i++) out[i] = vals[i];
        for (int i = 5; i < out_size; i++) out[i] = 0.f;
    }
}

// ---------------------------------------------------------------------------
// Host orchestration
// ---------------------------------------------------------------------------
static inline dim3 ggrid(int M, int N, int batch) {
    return dim3(N / 128, (M + 127) / 128, batch);
}

struct Scratch {
    float *h, *xln, *qkv, *q, *k, *v, *ql, *kl, *a1, *a3, *a2;
    float *z, *z2, *xz, *tA, *av, *zav, *O, *merged, *outp, *wrnd, *scal;
};

static void run_attention(const Scratch& S, const float* qkv_w, const float* out_w,
                          const float* out_b, const float* res_w,
                          const float* ln_g, const float* ln_b) {
    const long long sQ = (long long)NP * DHEAD;
    const long long sL = (long long)LMK * DHEAD;
    const long long sA1 = (long long)NP * LMK;
    const long long sA3 = (long long)LMK * NP;
    const long long sZZ = (long long)LMK * LMK;

    ln_pad<<<NP, 256>>>(S.h, S.xln, ln_g, ln_b);
    rnd_copy<<<(3072 * 1024 + 255) / 256, 256>>>(qkv_w, S.wrnd, 3072 * 1024);
    gemm_tc<true><<<ggrid(NP, 3072, 1), 256, SMEM_T_BYTES>>>(
        S.xln, S.wrnd, S.qkv, NP, 3072, DIM, DIM, DIM, 3072, 0, 0, 0, nullptr, 1.f, 0.f, nullptr, 0.f, 0);
    split_qkv<<<NP, 256>>>(S.qkv, S.q, S.k, S.v);
    landmarks<<<dim3(LMK, HEADS), DHEAD>>>(S.q, S.ql);
    landmarks<<<dim3(LMK, HEADS), DHEAD>>>(S.k, S.kl);

    gemm_tc<true><<<ggrid(NP, LMK, HEADS), 256, SMEM_T_BYTES>>>(
        S.q, S.kl, S.a1, NP, LMK, DHEAD, DHEAD, DHEAD, LMK, sQ, sL, sA1, nullptr, 1.f, 0.f, nullptr, 0.f, 0);
    row_softmax_r<2><<<HEADS * NP, 256>>>(S.a1, LMK);
    gemm_tc<true><<<ggrid(LMK, LMK, HEADS), 256, SMEM_T_BYTES>>>(
        S.ql, S.kl, S.a2, LMK, LMK, DHEAD, DHEAD, DHEAD, LMK, sL, sL, sZZ, nullptr, 1.f, 0.f, nullptr, 0.f, 0);
    row_softmax_r<2><<<HEADS * LMK, 256>>>(S.a2, LMK);
    gemm_tc<true><<<ggrid(LMK, NP, HEADS), 256, SMEM_T_BYTES>>>(
        S.ql, S.k, S.a3, LMK, NP, DHEAD, DHEAD, DHEAD, NP, sL, sQ, sA3, nullptr, 1.f, 0.f, nullptr, 0.f, 0);
    row_softmax_r<24><<<HEADS * LMK, 256>>>(S.a3, NP);

    // pinv(a2) via Newton-Schulz; all chained outputs tf32-rounded (rndC=1)
    scal_init<<<1, 32>>>(S.scal);
    a2_scal<<<HEADS, LMK>>>(S.a2, S.scal);
    zinit<<<dim3(LMK, HEADS), 256>>>(S.a2, S.z, S.scal);
    float* za = S.z;
    float* zb = S.z2;
    for (int it = 0; it < NITERS; it++) {
        gemm_tc<false><<<ggrid(LMK, LMK, HEADS), 256, SMEM_N_BYTES>>>(
            S.a2, za, S.xz, LMK, LMK, LMK, LMK, LMK, LMK, sZZ, sZZ, sZZ, nullptr, 1.f, 0.f, S.tA, 7.f, 1);
        gemm_tc<false><<<ggrid(LMK, LMK, HEADS), 256, SMEM_N_BYTES>>>(
            S.xz, S.tA, zb, LMK, LMK, LMK, LMK, LMK, LMK, sZZ, sZZ, sZZ, nullptr, -1.f, 15.f, nullptr, 0.f, 1);
        gemm_tc<false><<<ggrid(LMK, LMK, HEADS), 256, SMEM_N_BYTES>>>(
            S.xz, zb, S.tA, LMK, LMK, LMK, LMK, LMK, LMK, sZZ, sZZ, sZZ, nullptr, -1.f, 13.f, nullptr, 0.f, 1);
        gemm_tc<false><<<ggrid(LMK, LMK, HEADS), 256, SMEM_N_BYTES>>>(
            za, S.tA, zb, LMK, LMK, LMK, LMK, LMK, LMK, sZZ, sZZ, sZZ, nullptr, 0.25f, 0.f, nullptr, 0.f, 1);
        float* t = za; za = zb; zb = t;
    }

    // av = a3 @ v with split-K (partials in g_a2, dead after pinv; add3 rounds)
    {
        const int KC = 2048;
        for (int c = 0; c < 3; c++) {
            gemm_tc<false><<<dim3(1, 4, HEADS), 256, SMEM_N_BYTES>>>(
                S.a3 + (long long)c * KC,
                S.v + (long long)c * KC * DHEAD,
                S.a2 + (long long)c * HEADS * sL,
                LMK, DHEAD, KC, NP, DHEAD, DHEAD,
                sA3, sQ, sL, nullptr, 1.f, 0.f, nullptr, 0.f, 0);
        }
        int n = HEADS * LMK * DHEAD;
        add3<<<(n + 255) / 256, 256>>>(S.a2, S.a2 + (long long)HEADS * sL,
                                       S.a2 + 2ll * HEADS * sL, S.av, n);
    }
    gemm_tc<false><<<ggrid(LMK, DHEAD, HEADS), 256, SMEM_N_BYTES>>>(
        za, S.av, S.zav, LMK, DHEAD, LMK, LMK, DHEAD, DHEAD, sZZ, sL, sL, nullptr, 1.f, 0.f, nullptr, 0.f, 1);
    gemm_tc<false><<<ggrid(NP, DHEAD, HEADS), 256, SMEM_N_BYTES>>>(
        S.a1, S.zav, S.O, NP, DHEAD, LMK, LMK, DHEAD, DHEAD, sA1, sL, sQ, nullptr, 1.f, 0.f, nullptr, 0.f, 0);

    res_conv_add<<<dim3(NP, HEADS), DHEAD>>>(S.v, res_w, S.O);
    merge_heads<<<NP, 256>>>(S.O, S.merged);
    rnd_copy<<<(1024 * 1024 + 255) / 256, 256>>>(out_w, S.wrnd, 1024 * 1024);
    gemm_tc<true><<<ggrid(NP, DIM, 1), 256, SMEM_T_BYTES>>>(
        S.merged, S.wrnd, S.outp, NP, DIM, DIM, DIM, DIM, DIM, 0, 0, 0, out_b, 1.f, 0.f, nullptr, 0.f, 0);
    resid_add<<<(int)(((long long)HT * DIM + 255) / 256), 256>>>(S.h, S.outp);
}

extern "C" void kernel_launch(void* const* d_in, const int* in_sizes, int n_in,
                              void* d_out, int out_size) {
    cudaFuncSetAttribute(gemm_tc<true>,  cudaFuncAttributeMaxDynamicSharedMemorySize, SMEM_T_BYTES);
    cudaFuncSetAttribute(gemm_tc<false>, cudaFuncAttributeMaxDynamicSharedMemorySize, SMEM_N_BYTES);

    Scratch S;
    cudaGetSymbolAddress((void**)&S.h, g_h);
    cudaGetSymbolAddress((void**)&S.xln, g_xln);
    cudaGetSymbolAddress((void**)&S.qkv, g_qkv);
    cudaGetSymbolAddress((void**)&S.q, g_q);
    cudaGetSymbolAddress((void**)&S.k, g_k);
    cudaGetSymbolAddress((void**)&S.v, g_v);
    cudaGetSymbolAddress((void**)&S.ql, g_ql);
    cudaGetSymbolAddress((void**)&S.kl, g_kl);
    cudaGetSymbolAddress((void**)&S.a1, g_a1);
    cudaGetSymbolAddress((void**)&S.a3, g_a3);
    cudaGetSymbolAddress((void**)&S.a2, g_a2);
    cudaGetSymbolAddress((void**)&S.z, g_z);
    cudaGetSymbolAddress((void**)&S.z2, g_z2);
    cudaGetSymbolAddress((void**)&S.xz, g_xz);
    cudaGetSymbolAddress((void**)&S.tA, g_tA);
    cudaGetSymbolAddress((void**)&S.av, g_av);
    cudaGetSymbolAddress((void**)&S.zav, g_zav);
    cudaGetSymbolAddress((void**)&S.O, g_O);
    cudaGetSymbolAddress((void**)&S.merged, g_merged);
    cudaGetSymbolAddress((void**)&S.outp, g_outp);
    cudaGetSymbolAddress((void**)&S.wrnd, g_wrnd);
    cudaGetSymbolAddress((void**)&S.scal, g_scal);
    float* p_moe  = S.qkv;
    float* p_ftmp = S.xln;

    const bool sig = (n_in > 11 && in_sizes[11] > 10000);
    const float* data     = (const float*)d_in[0];
    const float* w_gate   = (const float*)d_in[1];
    const float* expert_w = (const float*)d_in[2];
    const float* expert_b = (const float*)d_in[3];
    const float* cls_tok  = (const float*)d_in[4];
    const float* ln1_g    = (const float*)d_in[5];
    const float* ln1_b    = (const float*)d_in[6];
    const float* qkv1_w   = (const float*)d_in[7];
    const float* out1_w   = (const float*)d_in[8];
    const float* out1_b   = (const float*)d_in[9];
    const float* res1_w   = (const float*)d_in[10];
    const float *pw7, *pb7, *pw5, *pb5, *pw3, *pb3;
    const float *ln2_g, *ln2_b, *qkv2_w, *out2_w, *out2_b, *res2_w;
    const float *normf_g, *normf_b, *fc2_w, *fc2_b;
    if (sig) {
        pw7 = (const float*)d_in[11]; pb7 = (const float*)d_in[12];
        pw5 = (const float*)d_in[13]; pb5 = (const float*)d_in[14];
        pw3 = (const float*)d_in[15]; pb3 = (const float*)d_in[16];
        ln2_g = (const float*)d_in[17]; ln2_b = (const float*)d_in[18];
        qkv2_w = (const float*)d_in[19]; out2_w = (const float*)d_in[20];
        out2_b = (const float*)d_in[21]; res2_w = (const float*)d_in[22];
        normf_g = (const float*)d_in[23]; normf_b = (const float*)d_in[24];
        fc2_w = (const float*)d_in[25]; fc2_b = (const float*)d_in[26];
    } else {
        ln2_g = (const float*)d_in[11]; ln2_b = (const float*)d_in[12];
        qkv2_w = (const float*)d_in[13]; out2_w = (const float*)d_in[14];
        out2_b = (const float*)d_in[15]; res2_w = (const float*)d_in[16];
        pw7 = (const float*)d_in[17]; pb7 = (const float*)d_in[18];
        pw5 = (const float*)d_in[19]; pb5 = (const float*)d_in[20];
        pw3 = (const float*)d_in[21]; pb3 = (const float*)d_in[22];
        normf_g = (const float*)d_in[23]; normf_b = (const float*)d_in[24];
        fc2_w = (const float*)d_in[25]; fc2_b = (const float*)d_in[26];
    }

    // 1. MoE — rounded copies of data (A) and expert_w (B)
    {
        const int ND = N0 * IND;
        const int NE = 3 * DIM * IND;
        rnd_copy<<<(ND + 255) / 256, 256>>>(data, S.wrnd, ND);
        rnd_copy<<<(NE + 255) / 256, 256>>>(expert_w, S.wrnd + ND, NE);
        gemm_tc<true><<<ggrid(N0, 3072, 1), 256, SMEM_T_BYTES>>>(
            S.wrnd, S.wrnd + ND, p_moe, N0, 3072, IND, IND, IND, 3072, 0, 0, 0, nullptr, 1.f, 0.f, nullptr, 0.f, 0);
    }
    moe_combine<<<N0, 256>>>(data, w_gate, p_moe, expert_b, S.h);
    set_cls<<<4, 256>>>(S.h, cls_tok);

    // 2. Attention block 1
    run_attention(S, qkv1_w, out1_w, out1_b, res1_w, ln1_g, ln1_b);

    // 3. PPEG
    copy_feat<<<NF, 256>>>(S.h, p_ftmp);
    ppeg_conv<<<NF, 256>>>(S.h, p_ftmp, pw7, pb7, pw5, pb5, pw3, pb3);

    // 4. Attention block 2
    run_attention(S, qkv2_w, out2_w, out2_b, res2_w, ln2_g, ln2_b);

    // 5. Head
    final_head<<<1, 256>>>(S.h, normf_g, normf_b, fc2_w, fc2_b, (float*)d_out, out_size);
}

// round 16
// speedup vs baseline: 1.1941x; 1.1941x over previous
#include <cuda_runtime.h>
#include <math.h>
#include <stdint.h>

// ---------------------------------------------------------------------------
// Problem constants
// ---------------------------------------------------------------------------
#define N0     6000
#define IND    1536
#define DIM    1024
#define HEADS  8
#define DHEAD  128
#define LMK    512
#define NITERS 6
#define HH     78
#define NF     (HH*HH)       // 6084
#define ADD    (NF - N0)     // 84
#define HT     (NF + 1)      // 6085
#define NP     6144
#define PAD    (NP - HT)     // 59
#define LFAC   (NP / LMK)    // 12

// ---------------------------------------------------------------------------
// Scratch (device globals; no allocation allowed).
// g_wrnd: tf32-rounded copies of raw inputs (data/expert_w/qkv_w/out_w)
// g_O   : also holds av split-K partials (dead until the O GEMM, post-join)
// ---------------------------------------------------------------------------
__device__ float g_h[(size_t)HT * DIM];
__device__ float g_xln[(size_t)NP * DIM];
__device__ float g_qkv[(size_t)NP * 3072];
__device__ float g_q[(size_t)HEADS * NP * DHEAD];
__device__ float g_k[(size_t)HEADS * NP * DHEAD];
__device__ float g_v[(size_t)HEADS * NP * DHEAD];
__device__ float g_ql[(size_t)HEADS * LMK * DHEAD];
__device__ float g_kl[(size_t)HEADS * LMK * DHEAD];
__device__ float g_a1[(size_t)HEADS * NP * LMK];
__device__ float g_a3[(size_t)HEADS * LMK * NP];
__device__ float g_a2[(size_t)HEADS * LMK * LMK];
__device__ float g_z[(size_t)HEADS * LMK * LMK];
__device__ float g_z2[(size_t)HEADS * LMK * LMK];
__device__ float g_xz[(size_t)HEADS * LMK * LMK];
__device__ float g_tA[(size_t)HEADS * LMK * LMK];
__device__ float g_av[(size_t)HEADS * LMK * DHEAD];
__device__ float g_zav[(size_t)HEADS * LMK * DHEAD];
__device__ float g_O[(size_t)HEADS * NP * DHEAD];
__device__ float g_merged[(size_t)NP * DIM];
__device__ float g_outp[(size_t)NP * DIM];
__device__ float g_wrnd[(size_t)14000000];
__device__ float g_scal[4];

// ---------------------------------------------------------------------------
// tf32 rounding helper (round-to-nearest-even into fp32 container)
// ---------------------------------------------------------------------------
__device__ __forceinline__ float rnd_tf32(float x) {
    uint32_t r;
    asm("cvt.rna.tf32.f32 %0, %1;" : "=r"(r) : "f"(x));
    return __uint_as_float(r);
}

__global__ void rnd_copy(const float* __restrict__ in, float* __restrict__ out, int n) {
    int i = blockIdx.x * blockDim.x + threadIdx.x;
    if (i < n) out[i] = rnd_tf32(in[i]);
}

// ---------------------------------------------------------------------------
// Reductions
// ---------------------------------------------------------------------------
__device__ __forceinline__ float warpSum(float v) {
#pragma unroll
    for (int o = 16; o > 0; o >>= 1) v += __shfl_xor_sync(0xffffffffu, v, o);
    return v;
}
__device__ __forceinline__ float warpMax(float v) {
#pragma unroll
    for (int o = 16; o > 0; o >>= 1) v = fmaxf(v, __shfl_xor_sync(0xffffffffu, v, o));
    return v;
}
__device__ float blockSum(float v, float* sh) {
    int lane = threadIdx.x & 31, wid = threadIdx.x >> 5;
    v = warpSum(v);
    __syncthreads();
    if (lane == 0) sh[wid] = v;
    __syncthreads();
    int nw = (blockDim.x + 31) >> 5;
    if (threadIdx.x < 32) {
        float r = (threadIdx.x < nw) ? sh[threadIdx.x] : 0.f;
        r = warpSum(r);
        if (threadIdx.x == 0) sh[0] = r;
    }
    __syncthreads();
    return sh[0];
}
__device__ float blockMax(float v, float* sh) {
    int lane = threadIdx.x & 31, wid = threadIdx.x >> 5;
    v = warpMax(v);
    __syncthreads();
    if (lane == 0) sh[wid] = v;
    __syncthreads();
    int nw = (blockDim.x + 31) >> 5;
    if (threadIdx.x < 32) {
        float r = (threadIdx.x < nw) ? sh[threadIdx.x] : -3.4e38f;
        r = warpMax(r);
        if (threadIdx.x == 0) sh[0] = r;
    }
    __syncthreads();
    return sh[0];
}

// ---------------------------------------------------------------------------
// Tensor-core GEMM (tf32 mma.sync, fp32 accumulate), cp.async 4-stage pipeline
// Block tile 128x128x16, 256 threads = 8 warps (2x4), warp tile 64x32.
// All operands pre-rounded to tf32, so the MMA's truncation is exact.
// ---------------------------------------------------------------------------
#define SPA 20
#define SPB 136
#define ASZ (128 * SPA)
#define BSZ_T (128 * SPA)
#define BSZ_N (16 * SPB)
#define STAGES 4

static constexpr int SMEM_T_BYTES = STAGES * (ASZ + BSZ_T) * 4;  // 81920
static constexpr int SMEM_N_BYTES = STAGES * (ASZ + BSZ_N) * 4;  // 75776

__device__ __forceinline__ void cp16(uint32_t saddr, const void* gaddr, int sz) {
    asm volatile("cp.async.cg.shared.global [%0], [%1], 16, %2;"
                 :: "r"(saddr), "l"(gaddr), "r"(sz) : "memory");
}
__device__ __forceinline__ void cp_commit() {
    asm volatile("cp.async.commit_group;" ::: "memory");
}
__device__ __forceinline__ void cp_wait2() {
    asm volatile("cp.async.wait_group 2;" ::: "memory");
}
__device__ __forceinline__ void mma8(float* c, const uint32_t* a, const uint32_t* b) {
    asm volatile(
        "mma.sync.aligned.m16n8k8.row.col.f32.tf32.tf32.f32 "
        "{%0,%1,%2,%3}, {%4,%5,%6,%7}, {%8,%9}, {%0,%1,%2,%3};"
        : "+f"(c[0]), "+f"(c[1]), "+f"(c[2]), "+f"(c[3])
        : "r"(a[0]), "r"(a[1]), "r"(a[2]), "r"(a[3]), "r"(b[0]), "r"(b[1]));
}

template <bool TRANSB>
__global__ __launch_bounds__(256) void gemm_tc(
    const float* __restrict__ A, const float* __restrict__ B,
    float* __restrict__ C, int M, int N, int K,
    int lda, int ldb, int ldc,
    long long sA, long long sB, long long sC,
    const float* __restrict__ bias, float alpha, float diag_c,
    float* __restrict__ C2, float diag2, int rndC)
{
    A += (long long)blockIdx.z * sA;
    B += (long long)blockIdx.z * sB;
    C += (long long)blockIdx.z * sC;
    if (C2) C2 += (long long)blockIdx.z * sC;

    extern __shared__ uint32_t smem[];
    constexpr int BSZ = TRANSB ? BSZ_T : BSZ_N;
    constexpr int STG = ASZ + BSZ;
    const uint32_t smem_base = (uint32_t)__cvta_generic_to_shared(smem);

    const int tid  = threadIdx.x;
    const int lane = tid & 31;
    const int warp = tid >> 5;
    const int wm   = warp & 1;
    const int wn   = warp >> 1;
    const int m0   = blockIdx.y * 128;
    const int n0   = blockIdx.x * 128;
    const int ntile = K >> 4;

    float acc[4][4][4];
#pragma unroll
    for (int i = 0; i < 4; i++)
#pragma unroll
        for (int j = 0; j < 4; j++)
#pragma unroll
            for (int l = 0; l < 4; l++) acc[i][j][l] = 0.f;

    auto prefetch = [&](int kt) {
        const int st = kt & (STAGES - 1);
        const int koff = kt << 4;
        const uint32_t sa = smem_base + (uint32_t)(st * STG) * 4u;
        const uint32_t sb = sa + (uint32_t)ASZ * 4u;
#pragma unroll
        for (int i = 0; i < 2; i++) {
            const int chunk = (tid << 1) + i;
            {
                const int row = chunk >> 2, kc = (chunk & 3) << 2;
                const float* src = A + (long long)(m0 + row) * lda + koff + kc;
                cp16(sa + (uint32_t)(row * SPA + kc) * 4u, src, (m0 + row < M) ? 16 : 0);
            }
            if (TRANSB) {
                const int row = chunk >> 2, kc = (chunk & 3) << 2;
                const float* src = B + (long long)(n0 + row) * ldb + koff + kc;
                cp16(sb + (uint32_t)(row * SPA + kc) * 4u, src, 16);
            } else {
                const int kr = chunk >> 5, nc = (chunk & 31) << 2;
                const float* src = B + (long long)(koff + kr) * ldb + n0 + nc;
                cp16(sb + (uint32_t)(kr * SPB + nc) * 4u, src, 16);
            }
        }
        cp_commit();
    };

#pragma unroll
    for (int p = 0; p < 3; p++) {
        if (p < ntile) prefetch(p);
        else cp_commit();
    }

    for (int kt = 0; kt < ntile; kt++) {
        cp_wait2();
        __syncthreads();
        const int st = kt & (STAGES - 1);
        const uint32_t* as = smem + st * STG;
        const uint32_t* bs = as + ASZ;
#pragma unroll
        for (int kk = 0; kk < 2; kk++) {
            const int c = (kk << 3) + (lane & 3);
            uint32_t af[4][4];
#pragma unroll
            for (int mf = 0; mf < 4; mf++) {
                const int r = (wm << 6) + (mf << 4) + (lane >> 2);
                af[mf][0] = as[(r    ) * SPA + c    ];
                af[mf][1] = as[(r + 8) * SPA + c    ];
                af[mf][2] = as[(r    ) * SPA + c + 4];
                af[mf][3] = as[(r + 8) * SPA + c + 4];
            }
            uint32_t bf[4][2];
#pragma unroll
            for (int nf = 0; nf < 4; nf++) {
                const int n = (wn << 5) + (nf << 3) + (lane >> 2);
                if (TRANSB) {
                    bf[nf][0] = bs[n * SPA + c    ];
                    bf[nf][1] = bs[n * SPA + c + 4];
                } else {
                    bf[nf][0] = bs[(c    ) * SPB + n];
                    bf[nf][1] = bs[(c + 4) * SPB + n];
                }
            }
#pragma unroll
            for (int mf = 0; mf < 4; mf++)
#pragma unroll
                for (int nf = 0; nf < 4; nf++)
                    mma8(acc[mf][nf], af[mf], bf[nf]);
        }
        if (kt + 3 < ntile) prefetch(kt + 3);
    }

    // epilogue
#pragma unroll
    for (int mf = 0; mf < 4; mf++) {
        const int rb = m0 + (wm << 6) + (mf << 4) + (lane >> 2);
#pragma unroll
        for (int nf = 0; nf < 4; nf++) {
            const int cb = n0 + (wn << 5) + (nf << 3) + ((lane & 3) << 1);
#pragma unroll
            for (int half = 0; half < 2; half++) {
                const int rr = rb + half * 8;
                if (rr >= M) continue;
#pragma unroll
                for (int e = 0; e < 2; e++) {
                    const int cc = cb + e;
                    float v = alpha * acc[mf][nf][half * 2 + e];
                    if (bias) v += bias[cc];
                    if (diag_c != 0.f && rr == cc) v += diag_c;
                    C[(long long)rr * ldc + cc] = rndC ? rnd_tf32(v) : v;
                    if (C2) {
                        float w = ((rr == cc) ? diag2 : 0.f) - v;
                        C2[(long long)rr * ldc + cc] = rndC ? rnd_tf32(w) : w;
                    }
                }
            }
        }
    }
}

// deterministic split-K reduce; output rounded (feeds zav GEMM)
__global__ void add3(const float* __restrict__ p0, const float* __restrict__ p1,
                     const float* __restrict__ p2, float* __restrict__ out, int n) {
    int i = blockIdx.x * blockDim.x + threadIdx.x;
    if (i < n) out[i] = rnd_tf32(p0[i] + p1[i] + p2[i]);
}

// ---------------------------------------------------------------------------
// Elementwise / reduction kernels (GEMM-feeding outputs tf32-rounded)
// ---------------------------------------------------------------------------
__global__ void moe_combine(const float* __restrict__ data, const float* __restrict__ wg,
                            const float* __restrict__ C, const float* __restrict__ eb,
                            float* __restrict__ hext) {
    int n = blockIdx.x;
    __shared__ float sh[32];
    float l0 = 0.f, l1 = 0.f, l2 = 0.f;
    const float* x = data + (long long)n * IND;
    for (int f = threadIdx.x; f < IND; f += blockDim.x) {
        float xv = x[f];
        l0 += xv * wg[f * 3 + 0];
        l1 += xv * wg[f * 3 + 1];
        l2 += xv * wg[f * 3 + 2];
    }
    l0 = blockSum(l0, sh);
    l1 = blockSum(l1, sh);
    l2 = blockSum(l2, sh);
    float m = fmaxf(l0, fmaxf(l1, l2));
    float e0 = __expf(l0 - m), e1 = __expf(l1 - m), e2 = __expf(l2 - m);
    float inv = 1.f / (e0 + e1 + e2);
    float gg0 = e0 * inv, gg1 = e1 * inv, gg2 = e2 * inv;
    const float* Cr = C + (long long)n * 3072;
    for (int o = threadIdx.x; o < DIM; o += blockDim.x) {
        float r = gg0 * fmaxf(Cr[o] + eb[o], 0.f)
                + gg1 * fmaxf(Cr[1024 + o] + eb[1024 + o], 0.f)
                + gg2 * fmaxf(Cr[2048 + o] + eb[2048 + o], 0.f);
        hext[(long long)(1 + n) * DIM + o] = r;
        if (n < ADD) hext[(long long)(1 + N0 + n) * DIM + o] = r;
    }
}

__global__ void set_cls(float* hext, const float* __restrict__ cls) {
    int c = blockIdx.x * blockDim.x + threadIdx.x;
    if (c < DIM) hext[c] = cls[c];
}

__global__ void ln_pad(const float* __restrict__ h, float* __restrict__ out,
                       const float* __restrict__ g, const float* __restrict__ b) {
    int r = blockIdx.x;
    float* o = out + (long long)r * DIM;
    if (r < PAD) {
        for (int c = threadIdx.x; c < DIM; c += blockDim.x) o[c] = 0.f;
        return;
    }
    const float* x = h + (long long)(r - PAD) * DIM;
    __shared__ float sh[32];
    float s = 0.f, s2 = 0.f;
    float xv[4];
#pragma unroll
    for (int i = 0; i < 4; i++) {
        float v = x[threadIdx.x + i * 256];
        xv[i] = v; s += v; s2 += v * v;
    }
    s = blockSum(s, sh);
    s2 = blockSum(s2, sh);
    float mu = s / DIM;
    float var = fmaxf(s2 / DIM - mu * mu, 0.f);
    float rstd = rsqrtf(var + 1e-5f);
#pragma unroll
    for (int i = 0; i < 4; i++) {
        int c = threadIdx.x + i * 256;
        o[c] = rnd_tf32((xv[i] - mu) * rstd * g[c] + b[c]);
    }
}

__global__ void split_qkv(const float* __restrict__ qkv, float* __restrict__ q,
                          float* __restrict__ k, float* __restrict__ v) {
    int n = blockIdx.x;
    const float* row = qkv + (long long)n * 3072;
    for (int c = threadIdx.x; c < 3072; c += blockDim.x) {
        float val = row[c];
        int which = c >> 10, cc = c & 1023;
        int h = cc >> 7, d = cc & 127;
        long long idx = ((long long)h * NP + n) * DHEAD + d;
        if (which == 0)      q[idx] = rnd_tf32(val * 0.08838834764831845f);
        else if (which == 1) k[idx] = rnd_tf32(val);
        else                 v[idx] = rnd_tf32(val);
    }
}

__global__ void landmarks(const float* __restrict__ q, float* __restrict__ ql) {
    int i = blockIdx.x, h = blockIdx.y, d = threadIdx.x;
    const float* base = q + ((long long)h * NP + (long long)i * LFAC) * DHEAD + d;
    float s = 0.f;
#pragma unroll
    for (int j = 0; j < LFAC; j++) s += base[(long long)j * DHEAD];
    ql[((long long)h * LMK + i) * DHEAD + d] = rnd_tf32(s * (1.f / LFAC));
}

// single-pass register softmax: 1 read + 1 write; output tf32-rounded.
template <int MAXC>
__global__ void row_softmax_r(float* __restrict__ X, int ncols) {
    float* x = X + (long long)blockIdx.x * ncols;
    __shared__ float sh[32];
    float loc[MAXC];
    const int nit = ncols >> 8;   // blockDim == 256
    float m = -3.4e38f;
#pragma unroll
    for (int i = 0; i < MAXC; i++) {
        if (i >= nit) break;
        loc[i] = x[threadIdx.x + (i << 8)];
        m = fmaxf(m, loc[i]);
    }
    m = blockMax(m, sh);
    float s = 0.f;
#pragma unroll
    for (int i = 0; i < MAXC; i++) {
        if (i >= nit) break;
        loc[i] = __expf(loc[i] - m);
        s += loc[i];
    }
    s = blockSum(s, sh);
    float inv = 1.f / s;
#pragma unroll
    for (int i = 0; i < MAXC; i++) {
        if (i >= nit) break;
        x[threadIdx.x + (i << 8)] = rnd_tf32(loc[i] * inv);
    }
}

__global__ void scal_init(float* scal) {
    if (threadIdx.x < 4) scal[threadIdx.x] = 0.f;
}

__global__ void a2_scal(const float* __restrict__ a2, float* scal) {
    int h = blockIdx.x;
    const float* A = a2 + (long long)h * LMK * LMK;
    int j = threadIdx.x;
    float rs = 0.f, cs = 0.f;
    for (int c = 0; c < LMK; c++) rs += A[(long long)j * LMK + c];
    for (int r = 0; r < LMK; r++) cs += A[(long long)r * LMK + j];
    __shared__ float sh[32];
    float rm = blockMax(rs, sh);
    float cm = blockMax(cs, sh);
    if (threadIdx.x == 0) {
        atomicMax((int*)&scal[0], __float_as_int(rm));
        atomicMax((int*)&scal[1], __float_as_int(cm));
    }
}

__global__ void zinit(const float* __restrict__ a2, float* __restrict__ z,
                      const float* __restrict__ scal) {
    int h = blockIdx.y, i = blockIdx.x;
    float inv = 1.f / (scal[0] * scal[1]);
    const float* A = a2 + (long long)h * LMK * LMK;
    float* Z = z + (long long)h * LMK * LMK;
    for (int j = threadIdx.x; j < LMK; j += blockDim.x)
        Z[(long long)i * LMK + j] = rnd_tf32(A[(long long)j * LMK + i] * inv);
}

__global__ void res_conv_add(const float* __restrict__ v, const float* __restrict__ w,
                             float* __restrict__ O) {
    int n = blockIdx.x, h = blockIdx.y, d = threadIdx.x;
    float acc = 0.f;
#pragma unroll
    for (int t = 0; t < 33; t++) {
        int nn = n + t - 16;
        if (nn >= 0 && nn < NP)
            acc += w[h * 33 + t] * v[((long long)h * NP + nn) * DHEAD + d];
    }
    O[((long long)h * NP + n) * DHEAD + d] += acc;
}

// merged feeds the out-proj GEMM: round
__global__ void merge_heads(const float* __restrict__ O, float* __restrict__ M_) {
    int n = blockIdx.x;
    for (int c = threadIdx.x; c < DIM; c += blockDim.x) {
        int h = c >> 7, d = c & 127;
        M_[(long long)n * DIM + c] = rnd_tf32(O[((long long)h * NP + n) * DHEAD + d]);
    }
}

__global__ void resid_add(float* __restrict__ h, const float* __restrict__ outp) {
    long long i = (long long)blockIdx.x * blockDim.x + threadIdx.x;
    if (i < (long long)HT * DIM) h[i] += outp[(long long)PAD * DIM + i];
}

__global__ void copy_feat(const float* __restrict__ h, float* __restrict__ f) {
    int s = blockIdx.x;
    for (int c = threadIdx.x; c < DIM; c += blockDim.x)
        f[(long long)s * DIM + c] = h[(long long)(1 + s) * DIM + c];
}

__global__ void ppeg_conv(float* __restrict__ h, const float* __restrict__ f,
                          const float* __restrict__ w7, const float* __restrict__ b7,
                          const float* __restrict__ w5, const float* __restrict__ b5,
                          const float* __restrict__ w3, const float* __restrict__ b3) {
    int s = blockIdx.x;
    int i = s / HH, j = s % HH;
    for (int c = threadIdx.x; c < DIM; c += blockDim.x) {
        float acc = f[(long long)s * DIM + c] + b7[c] + b5[c] + b3[c];
#pragma unroll
        for (int u = 0; u < 7; u++) {
            int ii = i + u - 3;
            if (ii < 0 || ii >= HH) continue;
#pragma unroll
            for (int vv = 0; vv < 7; vv++) {
                int jj = j + vv - 3;
                if (jj < 0 || jj >= HH) continue;
                acc += w7[c * 49 + u * 7 + vv] * f[(long long)(ii * HH + jj) * DIM + c];
            }
        }
#pragma unroll
        for (int u = 0; u < 5; u++) {
            int ii = i + u - 2;
            if (ii < 0 || ii >= HH) continue;
#pragma unroll
            for (int vv = 0; vv < 5; vv++) {
                int jj = j + vv - 2;
                if (jj < 0 || jj >= HH) continue;
                acc += w5[c * 25 + u * 5 + vv] * f[(long long)(ii * HH + jj) * DIM + c];
            }
        }
#pragma unroll
        for (int u = 0; u < 3; u++) {
            int ii = i + u - 1;
            if (ii < 0 || ii >= HH) continue;
#pragma unroll
            for (int vv = 0; vv < 3; vv++) {
                int jj = j + vv - 1;
                if (jj < 0 || jj >= HH) continue;
                acc += w3[c * 9 + u * 3 + vv] * f[(long long)(ii * HH + jj) * DIM + c];
            }
        }
        h[(long long)(1 + s) * DIM + c] = acc;
    }
}

__global__ void final_head(const float* __restrict__ h, const float* __restrict__ g,
                           const float* __restrict__ b, const float* __restrict__ fw,
                           const float* __restrict__ fb, float* __restrict__ out,
                           int out_size) {
    __shared__ float sh[32];
    float s = 0.f, s2 = 0.f;
    float xv[4];
#pragma unroll
    for (int i = 0; i < 4; i++) {
        float v = h[threadIdx.x + i * 256];
        xv[i] = v; s += v; s2 += v * v;
    }
    s = blockSum(s, sh);
    s2 = blockSum(s2, sh);
    float mu = s / DIM;
    float var = fmaxf(s2 / DIM - mu * mu, 0.f);
    float rstd = rsqrtf(var + 1e-5f);
    float d0 = 0.f, d1 = 0.f;
#pragma unroll
    for (int i = 0; i < 4; i++) {
        int c = threadIdx.x + i * 256;
        float xn = (xv[i] - mu) * rstd * g[c] + b[c];
        d0 += xn * fw[c];
        d1 += xn * fw[DIM + c];
    }
    d0 = blockSum(d0, sh);
    d1 = blockSum(d1, sh);
    if (threadIdx.x == 0) {
        float l0 = d0 + fb[0], l1 = d1 + fb[1];
        float m = fmaxf(l0, l1);
        float e0 = expf(l0 - m), e1 = expf(l1 - m);
        float inv = 1.f / (e0 + e1);
        float vals[5] = { l0, l1, e0 * inv, e1 * inv, (l1 > l0) ? 1.f : 0.f };
        for (int i = 0; i < 5 && i < out_size; i++) out[i] = vals[i];
        for (int i = 5; i < out_size; i++) out[i] = 0.f;
    }
}

// ---------------------------------------------------------------------------
// Host orchestration (dual-stream fork/join inside graph capture)
// ---------------------------------------------------------------------------
static inline dim3 ggrid(int M, int N, int batch) {
    return dim3(N / 128, (M + 127) / 128, batch);
}

struct Scratch {
    float *h, *xln, *qkv, *q, *k, *v, *ql, *kl, *a1, *a3, *a2;
    float *z, *z2, *xz, *tA, *av, *zav, *O, *merged, *outp, *wrnd, *scal;
};

// sa: main stream (big GEMMs). sb: pinv side stream.
static void run_attention(const Scratch& S, const float* qkv_w, const float* out_w,
                          const float* out_b, const float* res_w,
                          const float* ln_g, const float* ln_b,
                          cudaStream_t sa, cudaStream_t sb,
                          cudaEvent_t eL, cudaEvent_t ePinv) {
    const long long sQ = (long long)NP * DHEAD;
    const long long sL = (long long)LMK * DHEAD;
    const long long sA1 = (long long)NP * LMK;
    const long long sA3 = (long long)LMK * NP;
    const long long sZZ = (long long)LMK * LMK;

    ln_pad<<<NP, 256, 0, sa>>>(S.h, S.xln, ln_g, ln_b);
    rnd_copy<<<(3072 * 1024 + 255) / 256, 256, 0, sa>>>(qkv_w, S.wrnd, 3072 * 1024);
    gemm_tc<true><<<ggrid(NP, 3072, 1), 256, SMEM_T_BYTES, sa>>>(
        S.xln, S.wrnd, S.qkv, NP, 3072, DIM, DIM, DIM, 3072, 0, 0, 0, nullptr, 1.f, 0.f, nullptr, 0.f, 0);
    split_qkv<<<NP, 256, 0, sa>>>(S.qkv, S.q, S.k, S.v);
    landmarks<<<dim3(LMK, HEADS), DHEAD, 0, sa>>>(S.q, S.ql);
    landmarks<<<dim3(LMK, HEADS), DHEAD, 0, sa>>>(S.k, S.kl);
    cudaEventRecord(eL, sa);

    // ---- side stream: a2 + pinv chain ----
    cudaStreamWaitEvent(sb, eL, 0);
    gemm_tc<true><<<ggrid(LMK, LMK, HEADS), 256, SMEM_T_BYTES, sb>>>(
        S.ql, S.kl, S.a2, LMK, LMK, DHEAD, DHEAD, DHEAD, LMK, sL, sL, sZZ, nullptr, 1.f, 0.f, nullptr, 0.f, 0);
    row_softmax_r<2><<<HEADS * LMK, 256, 0, sb>>>(S.a2, LMK);
    scal_init<<<1, 32, 0, sb>>>(S.scal);
    a2_scal<<<HEADS, LMK, 0, sb>>>(S.a2, S.scal);
    zinit<<<dim3(LMK, HEADS), 256, 0, sb>>>(S.a2, S.z, S.scal);
    float* za = S.z;
    float* zb = S.z2;
    for (int it = 0; it < NITERS; it++) {
        gemm_tc<false><<<ggrid(LMK, LMK, HEADS), 256, SMEM_N_BYTES, sb>>>(
            S.a2, za, S.xz, LMK, LMK, LMK, LMK, LMK, LMK, sZZ, sZZ, sZZ, nullptr, 1.f, 0.f, S.tA, 7.f, 1);
        gemm_tc<false><<<ggrid(LMK, LMK, HEADS), 256, SMEM_N_BYTES, sb>>>(
            S.xz, S.tA, zb, LMK, LMK, LMK, LMK, LMK, LMK, sZZ, sZZ, sZZ, nullptr, -1.f, 15.f, nullptr, 0.f, 1);
        gemm_tc<false><<<ggrid(LMK, LMK, HEADS), 256, SMEM_N_BYTES, sb>>>(
            S.xz, zb, S.tA, LMK, LMK, LMK, LMK, LMK, LMK, sZZ, sZZ, sZZ, nullptr, -1.f, 13.f, nullptr, 0.f, 1);
        gemm_tc<false><<<ggrid(LMK, LMK, HEADS), 256, SMEM_N_BYTES, sb>>>(
            za, S.tA, zb, LMK, LMK, LMK, LMK, LMK, LMK, sZZ, sZZ, sZZ, nullptr, 0.25f, 0.f, nullptr, 0.f, 1);
        float* t = za; za = zb; zb = t;
    }
    cudaEventRecord(ePinv, sb);

    // ---- main stream: a1 / a3 / av path (concurrent with pinv) ----
    gemm_tc<true><<<ggrid(NP, LMK, HEADS), 256, SMEM_T_BYTES, sa>>>(
        S.q, S.kl, S.a1, NP, LMK, DHEAD, DHEAD, DHEAD, LMK, sQ, sL, sA1, nullptr, 1.f, 0.f, nullptr, 0.f, 0);
    row_softmax_r<2><<<HEADS * NP, 256, 0, sa>>>(S.a1, LMK);
    gemm_tc<true><<<ggrid(LMK, NP, HEADS), 256, SMEM_T_BYTES, sa>>>(
        S.ql, S.k, S.a3, LMK, NP, DHEAD, DHEAD, DHEAD, NP, sL, sQ, sA3, nullptr, 1.f, 0.f, nullptr, 0.f, 0);
    row_softmax_r<24><<<HEADS * LMK, 256, 0, sa>>>(S.a3, NP);

    // av = a3 @ v with split-K; partials in g_O (dead until O GEMM, post-join)
    {
        const int KC = 2048;
        for (int c = 0; c < 3; c++) {
            gemm_tc<false><<<dim3(1, 4, HEADS), 256, SMEM_N_BYTES, sa>>>(
                S.a3 + (long long)c * KC,
                S.v + (long long)c * KC * DHEAD,
                S.O + (long long)c * HEADS * sL,
                LMK, DHEAD, KC, NP, DHEAD, DHEAD,
                sA3, sQ, sL, nullptr, 1.f, 0.f, nullptr, 0.f, 0);
        }
        int n = HEADS * LMK * DHEAD;
        add3<<<(n + 255) / 256, 256, 0, sa>>>(S.O, S.O + (long long)HEADS * sL,
                                              S.O + 2ll * HEADS * sL, S.av, n);
    }

    // join: zav needs pinv result
    cudaStreamWaitEvent(sa, ePinv, 0);
    gemm_tc<false><<<ggrid(LMK, DHEAD, HEADS), 256, SMEM_N_BYTES, sa>>>(
        za, S.av, S.zav, LMK, DHEAD, LMK, LMK, DHEAD, DHEAD, sZZ, sL, sL, nullptr, 1.f, 0.f, nullptr, 0.f, 1);
    gemm_tc<false><<<ggrid(NP, DHEAD, HEADS), 256, SMEM_N_BYTES, sa>>>(
        S.a1, S.zav, S.O, NP, DHEAD, LMK, LMK, DHEAD, DHEAD, sA1, sL, sQ, nullptr, 1.f, 0.f, nullptr, 0.f, 0);

    res_conv_add<<<dim3(NP, HEADS), DHEAD, 0, sa>>>(S.v, res_w, S.O);
    merge_heads<<<NP, 256, 0, sa>>>(S.O, S.merged);
    rnd_copy<<<(1024 * 1024 + 255) / 256, 256, 0, sa>>>(out_w, S.wrnd, 1024 * 1024);
    gemm_tc<true><<<ggrid(NP, DIM, 1), 256, SMEM_T_BYTES, sa>>>(
        S.merged, S.wrnd, S.outp, NP, DIM, DIM, DIM, DIM, DIM, 0, 0, 0, out_b, 1.f, 0.f, nullptr, 0.f, 0);
    resid_add<<<(int)(((long long)HT * DIM + 255) / 256), 256, 0, sa>>>(S.h, S.outp);
}

extern "C" void kernel_launch(void* const* d_in, const int* in_sizes, int n_in,
                              void* d_out, int out_size) {
    cudaFuncSetAttribute(gemm_tc<true>,  cudaFuncAttributeMaxDynamicSharedMemorySize, SMEM_T_BYTES);
    cudaFuncSetAttribute(gemm_tc<false>, cudaFuncAttributeMaxDynamicSharedMemorySize, SMEM_N_BYTES);

    Scratch S;
    cudaGetSymbolAddress((void**)&S.h, g_h);
    cudaGetSymbolAddress((void**)&S.xln, g_xln);
    cudaGetSymbolAddress((void**)&S.qkv, g_qkv);
    cudaGetSymbolAddress((void**)&S.q, g_q);
    cudaGetSymbolAddress((void**)&S.k, g_k);
    cudaGetSymbolAddress((void**)&S.v, g_v);
    cudaGetSymbolAddress((void**)&S.ql, g_ql);
    cudaGetSymbolAddress((void**)&S.kl, g_kl);
    cudaGetSymbolAddress((void**)&S.a1, g_a1);
    cudaGetSymbolAddress((void**)&S.a3, g_a3);
    cudaGetSymbolAddress((void**)&S.a2, g_a2);
    cudaGetSymbolAddress((void**)&S.z, g_z);
    cudaGetSymbolAddress((void**)&S.z2, g_z2);
    cudaGetSymbolAddress((void**)&S.xz, g_xz);
    cudaGetSymbolAddress((void**)&S.tA, g_tA);
    cudaGetSymbolAddress((void**)&S.av, g_av);
    cudaGetSymbolAddress((void**)&S.zav, g_zav);
    cudaGetSymbolAddress((void**)&S.O, g_O);
    cudaGetSymbolAddress((void**)&S.merged, g_merged);
    cudaGetSymbolAddress((void**)&S.outp, g_outp);
    cudaGetSymbolAddress((void**)&S.wrnd, g_wrnd);
    cudaGetSymbolAddress((void**)&S.scal, g_scal);
    float* p_moe  = S.qkv;
    float* p_ftmp = S.xln;

    const bool sig = (n_in > 11 && in_sizes[11] > 10000);
    const float* data     = (const float*)d_in[0];
    const float* w_gate   = (const float*)d_in[1];
    const float* expert_w = (const float*)d_in[2];
    const float* expert_b = (const float*)d_in[3];
    const float* cls_tok  = (const float*)d_in[4];
    const float* ln1_g    = (const float*)d_in[5];
    const float* ln1_b    = (const float*)d_in[6];
    const float* qkv1_w   = (const float*)d_in[7];
    const float* out1_w   = (const float*)d_in[8];
    const float* out1_b   = (const float*)d_in[9];
    const float* res1_w   = (const float*)d_in[10];
    const float *pw7, *pb7, *pw5, *pb5, *pw3, *pb3;
    const float *ln2_g, *ln2_b, *qkv2_w, *out2_w, *out2_b, *res2_w;
    const float *normf_g, *normf_b, *fc2_w, *fc2_b;
    if (sig) {
        pw7 = (const float*)d_in[11]; pb7 = (const float*)d_in[12];
        pw5 = (const float*)d_in[13]; pb5 = (const float*)d_in[14];
        pw3 = (const float*)d_in[15]; pb3 = (const float*)d_in[16];
        ln2_g = (const float*)d_in[17]; ln2_b = (const float*)d_in[18];
        qkv2_w = (const float*)d_in[19]; out2_w = (const float*)d_in[20];
        out2_b = (const float*)d_in[21]; res2_w = (const float*)d_in[22];
        normf_g = (const float*)d_in[23]; normf_b = (const float*)d_in[24];
        fc2_w = (const float*)d_in[25]; fc2_b = (const float*)d_in[26];
    } else {
        ln2_g = (const float*)d_in[11]; ln2_b = (const float*)d_in[12];
        qkv2_w = (const float*)d_in[13]; out2_w = (const float*)d_in[14];
        out2_b = (const float*)d_in[15]; res2_w = (const float*)d_in[16];
        pw7 = (const float*)d_in[17]; pb7 = (const float*)d_in[18];
        pw5 = (const float*)d_in[19]; pb5 = (const float*)d_in[20];
        pw3 = (const float*)d_in[21]; pb3 = (const float*)d_in[22];
        normf_g = (const float*)d_in[23]; normf_b = (const float*)d_in[24];
        fc2_w = (const float*)d_in[25]; fc2_b = (const float*)d_in[26];
    }

    // Streams/events: created ONCE on the first call (the correctness run,
    // which precedes the harness's pre-capture memory baseline) and reused on
    // every call. Work enqueued per call is identical and deterministic; no
    // allocation happens during capture or replay, so the teardown baseline
    // matches. They intentionally live for the process lifetime.
    static cudaStream_t sa = nullptr, sb = nullptr;
    static cudaEvent_t e0, eL1, eP1, eL2, eP2, eEnd;
    if (sa == nullptr) {
        cudaStreamCreateWithFlags(&sa, cudaStreamNonBlocking);
        cudaStreamCreateWithFlags(&sb, cudaStreamNonBlocking);
        cudaEventCreateWithFlags(&e0,  cudaEventDisableTiming);
        cudaEventCreateWithFlags(&eL1, cudaEventDisableTiming);
        cudaEventCreateWithFlags(&eP1, cudaEventDisableTiming);
        cudaEventCreateWithFlags(&eL2, cudaEventDisableTiming);
        cudaEventCreateWithFlags(&eP2, cudaEventDisableTiming);
        cudaEventCreateWithFlags(&eEnd, cudaEventDisableTiming);
    }

    // fork from the capture-origin (null) stream
    cudaEventRecord(e0, 0);
    cudaStreamWaitEvent(sa, e0, 0);

    // 1. MoE (on sa)
    {
        const int ND = N0 * IND;
        const int NE = 3 * DIM * IND;
        rnd_copy<<<(ND + 255) / 256, 256, 0, sa>>>(data, S.wrnd, ND);
        rnd_copy<<<(NE + 255) / 256, 256, 0, sa>>>(expert_w, S.wrnd + ND, NE);
        gemm_tc<true><<<ggrid(N0, 3072, 1), 256, SMEM_T_BYTES, sa>>>(
            S.wrnd, S.wrnd + ND, p_moe, N0, 3072, IND, IND, IND, 3072, 0, 0, 0, nullptr, 1.f, 0.f, nullptr, 0.f, 0);
    }
    moe_combine<<<N0, 256, 0, sa>>>(data, w_gate, p_moe, expert_b, S.h);
    set_cls<<<4, 256, 0, sa>>>(S.h, cls_tok);

    // 2. Attention block 1 (sa main, sb pinv)
    run_attention(S, qkv1_w, out1_w, out1_b, res1_w, ln1_g, ln1_b, sa, sb, eL1, eP1);

    // 3. PPEG (sa)
    copy_feat<<<NF, 256, 0, sa>>>(S.h, p_ftmp);
    ppeg_conv<<<NF, 256, 0, sa>>>(S.h, p_ftmp, pw7, pb7, pw5, pb5, pw3, pb3);

    // 4. Attention block 2
    run_attention(S, qkv2_w, out2_w, out2_b, res2_w, ln2_g, ln2_b, sa, sb, eL2, eP2);

    // 5. Head (sa), then join back to the origin stream
    final_head<<<1, 256, 0, sa>>>(S.h, normf_g, normf_b, fc2_w, fc2_b, (float*)d_out, out_size);
    cudaEventRecord(eEnd, sa);
    cudaStreamWaitEvent(0, eEnd, 0);
}